// round 1
// baseline (speedup 1.0000x reference)
#include <cuda_runtime.h>
#include <cuda_bf16.h>
#include <cstdint>

#define DIM 1024
#define NGROUPS 32
#define GSIZE 32
#define TT 1024
#define BB 16
#define MROWS (TT * BB)          // 16384
#define BD (BB * DIM)            // 16384

// ---------------- scratch (device globals; no allocation allowed) ----------------
__device__ float g_vx[MROWS * DIM];
__device__ float g_alpha[MROWS * DIM];
__device__ float g_delta[MROWS * DIM];
__device__ float g_compete[MROWS * DIM];

// ---------------- helpers ----------------
__device__ __forceinline__ uint32_t f2tf32(float x) {
    uint32_t r;
    asm("cvt.rna.tf32.f32 %0, %1;" : "=r"(r) : "f"(x));
    return r;
}

__device__ __forceinline__ void mma_tf32(float* c, const uint32_t* a, const uint32_t* b) {
    asm volatile(
        "mma.sync.aligned.m16n8k8.row.col.f32.tf32.tf32.f32 "
        "{%0,%1,%2,%3}, {%4,%5,%6,%7}, {%8,%9}, {%0,%1,%2,%3};"
        : "+f"(c[0]), "+f"(c[1]), "+f"(c[2]), "+f"(c[3])
        : "r"(a[0]), "r"(a[1]), "r"(a[2]), "r"(a[3]), "r"(b[0]), "r"(b[1]));
}

// ---------------- GEMM: C[M,N] = A[M,K] @ W[N,K]^T, epilogue by mode ----------------
// mode 0: y = acc + bias[col]
// mode 1: y = 1 + softplus(acc + bias[col])
// mode 2: y = sigmoid(acc + bias[col])
// mode 3: y = compete[row*N+col] * silu(acc)
#define BM 128
#define BN 128
#define BK 16
#define PADA 4   // As[BM][BK+PADA]
#define PADB 4

__global__ void __launch_bounds__(256)
gemm_tf32_kernel(const float* __restrict__ A, const float* __restrict__ W,
                 const float* __restrict__ bias, const float* __restrict__ comp,
                 float* __restrict__ C, int M, int N, int K, int mode)
{
    __shared__ uint32_t As[BM][BK + PADA];
    __shared__ uint32_t Bs[BN][BK + PADB];

    const int tid  = threadIdx.x;
    const int lane = tid & 31;
    const int warp = tid >> 5;
    // 8 warps: 2 (M) x 4 (N); warp tile 64x32
    const int warpM = warp >> 2;   // 0..1
    const int warpN = warp & 3;    // 0..3
    const int wmBase = warpM * 64;
    const int wnBase = warpN * 32;

    const int m0 = blockIdx.y * BM;
    const int n0 = blockIdx.x * BN;

    // global-load mapping: tid -> (row = tid/4, 4-col chunk = (tid%4)*4), two passes (rows +0, +64)
    const int ldRow = tid >> 2;
    const int ldCol = (tid & 3) * 4;

    float acc[4][4][4];
#pragma unroll
    for (int i = 0; i < 4; i++)
#pragma unroll
        for (int j = 0; j < 4; j++)
#pragma unroll
            for (int r = 0; r < 4; r++) acc[i][j][r] = 0.f;

    const int grp = lane >> 2;   // 0..7
    const int tig = lane & 3;    // 0..3

    for (int k0 = 0; k0 < K; k0 += BK) {
        // stage global -> regs
        float4 a0 = *(const float4*)(A + (size_t)(m0 + ldRow) * K + k0 + ldCol);
        float4 a1 = *(const float4*)(A + (size_t)(m0 + ldRow + 64) * K + k0 + ldCol);
        float4 b0 = *(const float4*)(W + (size_t)(n0 + ldRow) * K + k0 + ldCol);
        float4 b1 = *(const float4*)(W + (size_t)(n0 + ldRow + 64) * K + k0 + ldCol);

        __syncthreads();   // previous iteration's compute done
        As[ldRow][ldCol + 0] = f2tf32(a0.x); As[ldRow][ldCol + 1] = f2tf32(a0.y);
        As[ldRow][ldCol + 2] = f2tf32(a0.z); As[ldRow][ldCol + 3] = f2tf32(a0.w);
        As[ldRow + 64][ldCol + 0] = f2tf32(a1.x); As[ldRow + 64][ldCol + 1] = f2tf32(a1.y);
        As[ldRow + 64][ldCol + 2] = f2tf32(a1.z); As[ldRow + 64][ldCol + 3] = f2tf32(a1.w);
        Bs[ldRow][ldCol + 0] = f2tf32(b0.x); Bs[ldRow][ldCol + 1] = f2tf32(b0.y);
        Bs[ldRow][ldCol + 2] = f2tf32(b0.z); Bs[ldRow][ldCol + 3] = f2tf32(b0.w);
        Bs[ldRow + 64][ldCol + 0] = f2tf32(b1.x); Bs[ldRow + 64][ldCol + 1] = f2tf32(b1.y);
        Bs[ldRow + 64][ldCol + 2] = f2tf32(b1.z); Bs[ldRow + 64][ldCol + 3] = f2tf32(b1.w);
        __syncthreads();

#pragma unroll
        for (int kk = 0; kk < BK; kk += 8) {
            uint32_t af[4][4];
#pragma unroll
            for (int mt = 0; mt < 4; mt++) {
                int r = wmBase + mt * 16 + grp;
                af[mt][0] = As[r][kk + tig];
                af[mt][1] = As[r + 8][kk + tig];
                af[mt][2] = As[r][kk + tig + 4];
                af[mt][3] = As[r + 8][kk + tig + 4];
            }
            uint32_t bf[4][2];
#pragma unroll
            for (int nt = 0; nt < 4; nt++) {
                int n = wnBase + nt * 8 + grp;
                bf[nt][0] = Bs[n][kk + tig];
                bf[nt][1] = Bs[n][kk + tig + 4];
            }
#pragma unroll
            for (int mt = 0; mt < 4; mt++)
#pragma unroll
                for (int nt = 0; nt < 4; nt++)
                    mma_tf32(acc[mt][nt], af[mt], bf[nt]);
        }
    }

    // epilogue
#pragma unroll
    for (int mt = 0; mt < 4; mt++) {
#pragma unroll
        for (int nt = 0; nt < 4; nt++) {
#pragma unroll
            for (int r = 0; r < 4; r++) {
                int row = m0 + wmBase + mt * 16 + grp + ((r >= 2) ? 8 : 0);
                int col = n0 + wnBase + nt * 8 + 2 * tig + (r & 1);
                float v = acc[mt][nt][r];
                float y;
                if (mode == 0) {
                    y = v + bias[col];
                } else if (mode == 1) {
                    float x = v + bias[col];
                    float sp = (x > 20.f) ? x : log1pf(__expf(x));
                    y = 1.0f + sp;
                } else if (mode == 2) {
                    float x = v + bias[col];
                    y = 1.0f / (1.0f + __expf(-x));
                } else {
                    float sil = v / (1.0f + __expf(-v));
                    y = comp[(size_t)row * N + col] * sil;
                }
                C[(size_t)row * N + col] = y;
            }
        }
    }
}

// ---------------- sequential scan (elementwise recurrence only) ----------------
// one warp per (b, group); thread handles one d. Writes h[0..T] into out_h [T+1,B,D].
__global__ void __launch_bounds__(256)
scan_kernel(const float* __restrict__ vx, const float* __restrict__ alpha,
            const float* __restrict__ delta, const float* __restrict__ h0,
            const float* __restrict__ r_h, float* __restrict__ out_h)
{
    int gtid = blockIdx.x * blockDim.x + threadIdx.x;   // 0..16383
    int b = gtid >> 10;            // /DIM
    int d = gtid & 1023;
    size_t base = (size_t)b * DIM + d;

    float rh = r_h[d];
    float h = h0[base];
    out_h[base] = h;               // h[0] = h0

    const int S = BD;              // stride per timestep
    float pvx[8], pal[8], pdl[8];
#pragma unroll
    for (int i = 0; i < 8; i++) {
        size_t off = (size_t)i * S + base;
        pvx[i] = __ldcs(vx + off);
        pal[i] = __ldcs(alpha + off);
        pdl[i] = __ldcs(delta + off);
    }

    for (int t0 = 0; t0 < TT; t0 += 8) {
#pragma unroll
        for (int i = 0; i < 8; i++) {
            int t = t0 + i;
            float vv = pvx[i], aa = pal[i], dd = pdl[i];
            int tn = t + 8;
            if (tn < TT) {
                size_t off = (size_t)tn * S + base;
                pvx[i] = __ldcs(vx + off);
                pal[i] = __ldcs(alpha + off);
                pdl[i] = __ldcs(delta + off);
            }
            float v = vv + rh * h;
            float av = fminf(fmaxf(fabsf(v), 1e-6f), 10.0f);
            float cand = __powf(av, aa);
            cand = (v >= 0.f) ? cand : -cand;
            if (v == 0.f) cand = 0.f;     // jnp.sign(0) == 0
            h = h + dd * (cand - h);
            out_h[(size_t)(t + 1) * S + base] = h;
        }
    }
}

// ---------------- compete = group softmax over h[1:], fully parallel ----------------
__global__ void __launch_bounds__(256)
compete_kernel(const float* __restrict__ h, float* __restrict__ comp)
{
    size_t idx = (size_t)blockIdx.x * blockDim.x + threadIdx.x;
    float v = h[idx];
    float m = v;
#pragma unroll
    for (int o = 16; o > 0; o >>= 1) m = fmaxf(m, __shfl_xor_sync(0xffffffffu, m, o));
    float e = __expf(v - m);
    float s = e;
#pragma unroll
    for (int o = 16; o > 0; o >>= 1) s += __shfl_xor_sync(0xffffffffu, s, o);
    comp[idx] = e / s;
}

// ---------------- launch ----------------
extern "C" void kernel_launch(void* const* d_in, const int* in_sizes, int n_in,
                              void* d_out, int out_size)
{
    const float* x       = (const float*)d_in[0];   // [T,B,D]
    const float* h0      = (const float*)d_in[1];   // [B,D]
    const float* W_x     = (const float*)d_in[2];   // [D,D]
    const float* r_h     = (const float*)d_in[3];   // [D]
    const float* b       = (const float*)d_in[4];   // [D]
    const float* W_alpha = (const float*)d_in[5];
    const float* b_alpha = (const float*)d_in[6];
    const float* W_delta = (const float*)d_in[7];
    const float* b_delta = (const float*)d_in[8];
    const float* W_out   = (const float*)d_in[9];

    float* out = (float*)d_out;
    float* out_h = out;                                  // [T+1,B,D]
    float* out_y = out + (size_t)(TT + 1) * BD;          // [T,B,D]

    float *vx, *al, *dl, *cp;
    cudaGetSymbolAddress((void**)&vx, g_vx);
    cudaGetSymbolAddress((void**)&al, g_alpha);
    cudaGetSymbolAddress((void**)&dl, g_delta);
    cudaGetSymbolAddress((void**)&cp, g_compete);

    dim3 ggrid(DIM / BN, MROWS / BM);   // (8, 128)
    // 1) projections
    gemm_tf32_kernel<<<ggrid, 256>>>(x, W_x,     b,       nullptr, vx, MROWS, DIM, DIM, 0);
    gemm_tf32_kernel<<<ggrid, 256>>>(x, W_alpha, b_alpha, nullptr, al, MROWS, DIM, DIM, 1);
    gemm_tf32_kernel<<<ggrid, 256>>>(x, W_delta, b_delta, nullptr, dl, MROWS, DIM, DIM, 2);
    // 2) sequential scan -> h states (written straight into d_out)
    scan_kernel<<<BD / 256, 256>>>(vx, al, dl, h0, r_h, out_h);
    // 3) group softmax over h[1:]
    compete_kernel<<<(MROWS * DIM) / 256, 256>>>(out_h + BD, cp);
    // 4) output GEMM with compete*silu epilogue
    gemm_tf32_kernel<<<ggrid, 256>>>(out_h + BD, W_out, nullptr, cp, out_y, MROWS, DIM, DIM, 3);
}